// round 17
// baseline (speedup 1.0000x reference)
#include <cuda_runtime.h>
#include <cuda_bf16.h>
#include <cuda_fp16.h>
#include <mma.h>
#include <math.h>
#include <stdint.h>

using namespace nvcuda;

#define N_NODES 100000
#define N_EDGES 1600000
#define HID 64
#define SCAN_BLOCKS ((N_NODES + 255) / 256)   // 391

// ---------------- scratch (static device memory; no allocations) ----------------
__device__ int     g_deg[N_NODES];               // steady-state ZERO between replays
__device__ float   g_dinv[N_NODES];
__device__ int     g_rowptr[N_NODES + 1];
__device__ int     g_fill[N_NODES];
__device__ int2    g_csr[N_EDGES];               // .x = src, .y = bits of norm weight
__device__ __half2 g_h1h[(size_t)N_NODES * 32];  // GEMM output (gather operand), fp16
__device__ __half2 g_h2h[(size_t)N_NODES * 32];  // agg output (GEMM input), fp16
__device__ int     g_blocksum[SCAN_BLOCKS];

// ---------------- preprocessing ----------------
__global__ void k_hist(const int* __restrict__ ei) {
    int e = blockIdx.x * blockDim.x + threadIdx.x;
    if (e < N_EDGES) {
        int d = ei[N_EDGES + e];
        if ((unsigned)d >= N_NODES) d = 0;
        atomicAdd(&g_deg[d], 1);
    }
}

// block-level exclusive scan of indeg; computes dinv (deg = indeg+1 self-loop)
// and RE-ZEROES g_deg for the next replay (replaces k_init_deg).
__global__ void k_blockscan() {
    __shared__ int wsum[8];
    int tid = threadIdx.x;
    int lane = tid & 31;
    int wid = tid >> 5;
    int i = blockIdx.x * 256 + tid;

    int e = 0;
    if (i < N_NODES) {
        int raw = g_deg[i];           // in-degree
        g_deg[i] = 0;                 // reset for next replay
        g_dinv[i] = rsqrtf((float)(raw + 1));
        e = raw;
    }
    int incl = e;
#pragma unroll
    for (int o = 1; o < 32; o <<= 1) {
        int v = __shfl_up_sync(0xffffffffu, incl, o);
        if (lane >= o) incl += v;
    }
    if (lane == 31) wsum[wid] = incl;
    __syncthreads();
    if (wid == 0) {
        int v = (lane < 8) ? wsum[lane] : 0;
        int s = v;
#pragma unroll
        for (int o = 1; o < 8; o <<= 1) {
            int u = __shfl_up_sync(0xffffffffu, s, o);
            if (lane >= o) s += u;
        }
        if (lane < 8) wsum[lane] = s - v;
    }
    __syncthreads();
    int excl = incl - e + wsum[wid];
    if (i < N_NODES) g_rowptr[i] = excl;          // block-local partial
    if (tid == 255) g_blocksum[blockIdx.x] = excl + e;
}

// merged scanmid+addoff: every block redundantly scans the 391 block sums
// (Hillis-Steele over 512 padded entries in smem), then applies its offset.
__global__ void k_scanoff() {
    __shared__ int ts[512];
    int tid = threadIdx.x;
    int b = blockIdx.x;
    ts[tid]       = (tid < SCAN_BLOCKS) ? g_blocksum[tid] : 0;
    ts[tid + 256] = (tid + 256 < SCAN_BLOCKS) ? g_blocksum[tid + 256] : 0;
    __syncthreads();
#pragma unroll
    for (int off = 1; off < 512; off <<= 1) {
        int a0 = (tid >= off) ? ts[tid - off] : 0;
        int i1 = tid + 256;
        int a1 = ts[i1 - off];     // i1 >= 256 >= off always
        __syncthreads();
        ts[tid] += a0;
        ts[i1] += a1;
        __syncthreads();
    }
    // inclusive scan now in ts; exclusive offset of block b = ts[b-1]
    int off = (b == 0) ? 0 : ts[b - 1];
    int i = b * 256 + tid;
    if (i < N_NODES) {
        int v = g_rowptr[i] + off;
        g_rowptr[i] = v;
        g_fill[i] = v;
    }
    if (b == SCAN_BLOCKS - 1 && tid == 0)
        g_rowptr[N_NODES] = ts[SCAN_BLOCKS - 1];
}

__global__ void k_scatter(const int* __restrict__ ei) {
    int e = blockIdx.x * blockDim.x + threadIdx.x;
    if (e < N_EDGES) {
        int s = ei[e];
        int d = ei[N_EDGES + e];
        if ((unsigned)s >= N_NODES) s = 0;
        if ((unsigned)d >= N_NODES) d = 0;
        int pos = atomicAdd(&g_fill[d], 1);
        if ((unsigned)pos < N_EDGES) {
            float w = g_dinv[s] * g_dinv[d];
            g_csr[pos] = make_int2(s, __float_as_int(w));
        }
    }
}

// ---------------- Layer-1 GEMM: fp16 wmma, K chunked by 128 ------------------
// g_h1h[N,64](fp16) = X[N,256](fp32) @ W[256,64](fp32), tile M=128 x N=64.
// KC=128: only 2 chunks (half R12's sync count) at 53.2KB dynamic smem ->
// 4 blocks/SM (double R16's residency -> more latency-hiding MLP).
__global__ void __launch_bounds__(256)
k_gemm1_f16(const float* __restrict__ Xp, const float* __restrict__ Wp) {
    constexpr int KC = 128;
    constexpr int LDA = 136;   // halves (KC + pad 8); row 272 B
    constexpr int LDB = 72;    // halves
    constexpr int LDC = 68;    // floats (epilogue alias of As region)
    extern __shared__ __align__(16) char sbuf[];
    __half* As = (__half*)sbuf;                         // 128*136*2 = 34816
    __half* Bs = (__half*)(sbuf + 128 * LDA * 2);       // 128*72*2  = 18432
    float*  Cs = (float*)sbuf;                          // 128*68*4  = 34816

    int tid = threadIdx.x;
    int wid = tid >> 5;
    int base = blockIdx.x * 128;
    int m0 = wid * 16;

    wmma::fragment<wmma::accumulator, 16, 16, 16, float> acc[4];
#pragma unroll
    for (int j = 0; j < 4; j++) wmma::fill_fragment(acc[j], 0.f);

    for (int c = 0; c < 2; c++) {
        __syncthreads();   // previous chunk consumed
        // stage A: 128 rows x 128 floats = 4096 float4, 16 per thread
#pragma unroll 4
        for (int it = 0; it < 16; it++) {
            int idx = tid + 256 * it;      // 0..4095
            int r = idx >> 5;              // row 0..127 (32 float4/row)
            int q = idx & 31;
            float4 v = make_float4(0.f, 0.f, 0.f, 0.f);
            int grow = base + r;
            if (grow < N_NODES)
                v = *(const float4*)&Xp[(size_t)grow * 256 + c * KC + q * 4];
            __half2 h[2];
            h[0] = __floats2half2_rn(v.x, v.y);
            h[1] = __floats2half2_rn(v.z, v.w);
            *(uint2*)&As[r * LDA + q * 4] = *(uint2*)h;
        }
        // stage B: 128 rows x 64 floats = 2048 float4, 8 per thread
#pragma unroll 4
        for (int it = 0; it < 8; it++) {
            int idx = tid + 256 * it;      // 0..2047
            int k = idx >> 4;              // row 0..127
            int q = idx & 15;
            float4 v = *(const float4*)&Wp[(size_t)(c * KC + k) * 64 + q * 4];
            __half2 h[2];
            h[0] = __floats2half2_rn(v.x, v.y);
            h[1] = __floats2half2_rn(v.z, v.w);
            *(uint2*)&Bs[k * LDB + q * 4] = *(uint2*)h;
        }
        __syncthreads();

        // 8 k-steps of 16
#pragma unroll
        for (int kk = 0; kk < 8; kk++) {
            wmma::fragment<wmma::matrix_a, 16, 16, 16, __half, wmma::row_major> a;
            wmma::load_matrix_sync(a, &As[m0 * LDA + kk * 16], LDA);
#pragma unroll
            for (int j = 0; j < 4; j++) {
                wmma::fragment<wmma::matrix_b, 16, 16, 16, __half, wmma::row_major> b;
                wmma::load_matrix_sync(b, &Bs[kk * 16 * LDB + j * 16], LDB);
                wmma::mma_sync(acc[j], a, b, acc[j]);
            }
        }
    }

    // epilogue: fragments -> Cs (fp32) -> g_h1h (fp16)
    __syncthreads();
#pragma unroll
    for (int j = 0; j < 4; j++)
        wmma::store_matrix_sync(&Cs[m0 * LDC + j * 16], acc[j], LDC,
                                wmma::mem_row_major);
    __syncthreads();
    {
        int r = tid >> 1;
        int half = tid & 1;
        int row = base + r;
        if (row < N_NODES) {
            const float* cr = &Cs[r * LDC + half * 32];
            __half2 h[16];
#pragma unroll
            for (int p = 0; p < 16; p++) {
                float2 f = *(const float2*)&cr[2 * p];
                h[p] = __floats2half2_rn(f.x, f.y);
            }
            uint4* o = (uint4*)&g_h1h[(size_t)row * 32 + half * 16];
#pragma unroll
            for (int q = 0; q < 4; q++) o[q] = ((uint4*)h)[q];
        }
    }
}

// ---------------- Layers 2/3 GEMM: fp16 wmma (A already fp16 in g_h2h) -------
__global__ void __launch_bounds__(256, 3)
k_gemm_f16(const float* __restrict__ Wp) {
    constexpr int LDA = 72;
    constexpr int LDC = 68;
    __shared__ __align__(16) char sb[128 * LDC * 4];     // 34816 B
    __half* As = (__half*)sb;                            // 18432
    __half* Bs = (__half*)(sb + 128 * LDA * 2);          //  9216
    float*  Cs = (float*)sb;

    int tid = threadIdx.x;
    int wid = tid >> 5;
    int base = blockIdx.x * 128;
    int m0 = wid * 16;

    wmma::fragment<wmma::accumulator, 16, 16, 16, float> acc[4];
#pragma unroll
    for (int j = 0; j < 4; j++) wmma::fill_fragment(acc[j], 0.f);

    {
        const uint4* X = (const uint4*)g_h2h;
#pragma unroll
        for (int it = 0; it < 4; it++) {
            int idx = tid + 256 * it;
            int r = idx >> 3, k8 = idx & 7;
            uint4 v = make_uint4(0u, 0u, 0u, 0u);
            int grow = base + r;
            if (grow < N_NODES) v = X[(size_t)grow * 8 + k8];
            *(uint4*)&As[r * LDA + k8 * 8] = v;
        }
#pragma unroll
        for (int it = 0; it < 2; it++) {
            int idx = tid + 256 * it;
            int k = idx >> 3, n8 = idx & 7;
            const float* wr = &Wp[(size_t)k * 64 + n8 * 8];
            float4 v0 = *(const float4*)wr;
            float4 v1 = *(const float4*)(wr + 4);
            __half2 h[4];
            h[0] = __floats2half2_rn(v0.x, v0.y);
            h[1] = __floats2half2_rn(v0.z, v0.w);
            h[2] = __floats2half2_rn(v1.x, v1.y);
            h[3] = __floats2half2_rn(v1.z, v1.w);
            *(uint4*)&Bs[k * LDA + n8 * 8] = *(uint4*)h;
        }
    }
    __syncthreads();

#pragma unroll
    for (int kk = 0; kk < 4; kk++) {
        wmma::fragment<wmma::matrix_a, 16, 16, 16, __half, wmma::row_major> a;
        wmma::load_matrix_sync(a, &As[m0 * LDA + kk * 16], LDA);
#pragma unroll
        for (int j = 0; j < 4; j++) {
            wmma::fragment<wmma::matrix_b, 16, 16, 16, __half, wmma::row_major> b;
            wmma::load_matrix_sync(b, &Bs[kk * 16 * LDA + j * 16], LDA);
            wmma::mma_sync(acc[j], a, b, acc[j]);
        }
    }

    __syncthreads();
#pragma unroll
    for (int j = 0; j < 4; j++)
        wmma::store_matrix_sync(&Cs[m0 * LDC + j * 16], acc[j], LDC,
                                wmma::mem_row_major);
    __syncthreads();
    {
        int r = tid >> 1;
        int half = tid & 1;
        int row = base + r;
        if (row < N_NODES) {
            const float* cr = &Cs[r * LDC + half * 32];
            __half2 h[16];
#pragma unroll
            for (int p = 0; p < 16; p++) {
                float2 f = *(const float2*)&cr[2 * p];
                h[p] = __floats2half2_rn(f.x, f.y);
            }
            uint4* o = (uint4*)&g_h1h[(size_t)row * 32 + half * 16];
#pragma unroll
            for (int q = 0; q < 4; q++) o[q] = ((uint4*)h)[q];
        }
    }
}

// ---------------- Aggregation + epilogue: warp per node ----------------
// OUT[i] = sum_{e: dst=i} w_e * h1h[src_e] + dinv[i]^2 * h1h[i] + bias
// MODE=1: relu + L2-normalize -> g_h2h (fp16).  MODE=0: plain -> OUTp (fp32).
template <int MODE>
__global__ void k_agg(const float* __restrict__ bias, float* __restrict__ OUTp) {
    int gwarp = (blockIdx.x * blockDim.x + threadIdx.x) >> 5;
    int lane = threadIdx.x & 31;
    if (gwarp >= N_NODES) return;
    int i = gwarp;

    float di = g_dinv[i];
    int beg = g_rowptr[i];
    int end = g_rowptr[i + 1];

    const __half2* __restrict__ H = g_h1h;
    float2 hv = __half22float2(H[(size_t)i * 32 + lane]);
    float wself = di * di;
    float a0 = wself * hv.x;
    float a1 = wself * hv.y;

    int j = beg;
    for (; j + 8 <= end; j += 8) {
        int2 e[8];
        float2 h[8];
#pragma unroll
        for (int q = 0; q < 8; q++) e[q] = g_csr[j + q];
#pragma unroll
        for (int q = 0; q < 8; q++)
            h[q] = __half22float2(H[(size_t)e[q].x * 32 + lane]);
#pragma unroll
        for (int q = 0; q < 8; q++) {
            float w = __int_as_float(e[q].y);
            a0 += w * h[q].x;
            a1 += w * h[q].y;
        }
    }
    for (; j < end; j++) {
        int2 sw = g_csr[j];
        float w = __int_as_float(sw.y);
        float2 hs = __half22float2(H[(size_t)sw.x * 32 + lane]);
        a0 += w * hs.x;
        a1 += w * hs.y;
    }

    float2 b = ((const float2*)bias)[lane];
    a0 += b.x;
    a1 += b.y;

    if (MODE == 1) {
        a0 = fmaxf(a0, 0.f);
        a1 = fmaxf(a1, 0.f);
        float ss = a0 * a0 + a1 * a1;
#pragma unroll
        for (int o = 16; o; o >>= 1) ss += __shfl_xor_sync(0xffffffffu, ss, o);
        float inv = 1.f / fmaxf(sqrtf(ss), 1e-12f);
        a0 *= inv;
        a1 *= inv;
        g_h2h[(size_t)i * 32 + lane] = __floats2half2_rn(a0, a1);
    } else {
        ((float2*)OUTp)[(size_t)i * 32 + lane] = make_float2(a0, a1);
    }
}

// ---------------- launch ----------------
extern "C" void kernel_launch(void* const* d_in, const int* in_sizes, int n_in,
                              void* d_out, int out_size) {
    const float* x = (const float*)d_in[0];
    const int* ei = (const int*)d_in[1];     // int32 edge_index [2, E]
    const float* W1 = (const float*)d_in[2];
    const float* b1 = (const float*)d_in[3];
    const float* W2 = (const float*)d_in[4];
    const float* b2 = (const float*)d_in[5];
    const float* W3 = (const float*)d_in[6];
    const float* b3 = (const float*)d_in[7];
    float* out = (float*)d_out;

    const int SMEM1 = (128 * 136 + 128 * 72) * 2;   // 53248 B
    cudaFuncSetAttribute(k_gemm1_f16,
                         cudaFuncAttributeMaxDynamicSharedMemorySize, SMEM1);

    const int T = 256;
    int gemm_grid = (N_NODES + 127) / 128;
    int agg_grid = (N_NODES * 32 + T - 1) / T;

    // preprocessing (g_deg starts zero; blockscan re-zeroes it each replay)
    k_hist<<<(N_EDGES + T - 1) / T, T>>>(ei);               // 0
    k_blockscan<<<SCAN_BLOCKS, T>>>();                      // 1
    k_scanoff<<<SCAN_BLOCKS, T>>>();                        // 2
    k_gemm1_f16<<<gemm_grid, 256, SMEM1>>>(x, W1);          // 3  <- profiled
    k_scatter<<<(N_EDGES + T - 1) / T, T>>>(ei);            // 4

    // layer 1 aggregation
    k_agg<1><<<agg_grid, T>>>(b1, nullptr);                 // 5
    // layer 2
    k_gemm_f16<<<gemm_grid, 256>>>(W2);                     // 6
    k_agg<1><<<agg_grid, T>>>(b2, nullptr);                 // 7
    // layer 3
    k_gemm_f16<<<gemm_grid, 256>>>(W3);                     // 8
    k_agg<0><<<agg_grid, T>>>(b3, out);                     // 9
}